// round 1
// baseline (speedup 1.0000x reference)
#include <cuda_runtime.h>
#include <cuda_bf16.h>

// QuantumKANRegressor: per (b,f): Chebyshev T1..T16 dot lcu_weights (normalized),
// tanh, Chebyshev T0..T5 dot kan_coeffs, sum over f -> out[b].
// X: [65536, 64] f32, lcu_weights: [64,16] f32, kan_coeffs: [1,64,6] f32, out: [65536,1] f32.

#define B_TOTAL 65536
#define F_DIM 64
#define DEG 16
#define KDEG 6            // KAN_DEG + 1 coefficients
#define THREADS 256
#define WARPS_PER_BLOCK 8
#define ROWS_PER_WARP 4

__global__ void __launch_bounds__(THREADS)
qkan_kernel(const float* __restrict__ X,
            const float* __restrict__ W,     // [64][16]
            const float* __restrict__ C,     // [64][6]
            float* __restrict__ out)
{
    __shared__ float s_wT[DEG * F_DIM];     // transposed: s_wT[d*64 + f]
    __shared__ float s_k[KDEG * F_DIM];     // transposed: s_k[k*64 + f]
    __shared__ float s_invden[F_DIM];

    const int tid = threadIdx.x;

    // Stage lcu weights transposed (coalesced global read).
    #pragma unroll
    for (int idx = tid; idx < DEG * F_DIM; idx += THREADS) {
        int f = idx >> 4;          // /16
        int d = idx & 15;
        s_wT[d * F_DIM + f] = W[idx];
    }
    // Stage KAN coeffs transposed.
    #pragma unroll
    for (int idx = tid; idx < KDEG * F_DIM; idx += THREADS) {
        int f = idx / KDEG;
        int k = idx - f * KDEG;
        s_k[k * F_DIM + f] = C[idx];
    }
    // Per-feature 1/sum|w|.
    if (tid < F_DIM) {
        float den = 0.0f;
        #pragma unroll
        for (int d = 0; d < DEG; d++) den += fabsf(W[tid * DEG + d]);
        s_invden[tid] = 1.0f / den;
    }
    __syncthreads();

    const int warp = tid >> 5;
    const int lane = tid & 31;
    const int fa = lane;
    const int fb = lane + 32;
    const int row0 = (blockIdx.x * WARPS_PER_BLOCK + warp) * ROWS_PER_WARP;

    // Issue all global loads up front (MLP=8).
    float xa[ROWS_PER_WARP], xb[ROWS_PER_WARP];
    #pragma unroll
    for (int r = 0; r < ROWS_PER_WARP; r++) {
        const float* px = X + (size_t)(row0 + r) * F_DIM;
        xa[r] = px[fa];
        xb[r] = px[fb];
    }

    const float inv_a = s_invden[fa];
    const float inv_b = s_invden[fb];

    #pragma unroll
    for (int r = 0; r < ROWS_PER_WARP; r++) {
        // ---- feature fa ----
        float part;
        {
            float x = xa[r];
            float x2 = 2.0f * x;
            float Tp = 1.0f, Tc = x, acc = 0.0f;
            #pragma unroll
            for (int d = 0; d < DEG; d++) {
                acc = fmaf(s_wT[d * F_DIM + fa], Tc, acc);
                float Tn = fmaf(x2, Tc, -Tp);
                Tp = Tc; Tc = Tn;
            }
            float feat = acc * inv_a;
            float e = __expf(2.0f * feat);            // |feat| <= 1
            float z = __fdividef(e - 1.0f, e + 1.0f); // tanh(feat)
            float o = fmaf(s_k[F_DIM + fa], z, s_k[fa]);
            float z2 = 2.0f * z;
            float Up = 1.0f, Uc = z;
            #pragma unroll
            for (int k = 2; k < KDEG; k++) {
                float Un = fmaf(z2, Uc, -Up);
                o = fmaf(s_k[k * F_DIM + fa], Un, o);
                Up = Uc; Uc = Un;
            }
            part = o;
        }
        // ---- feature fb ----
        {
            float x = xb[r];
            float x2 = 2.0f * x;
            float Tp = 1.0f, Tc = x, acc = 0.0f;
            #pragma unroll
            for (int d = 0; d < DEG; d++) {
                acc = fmaf(s_wT[d * F_DIM + fb], Tc, acc);
                float Tn = fmaf(x2, Tc, -Tp);
                Tp = Tc; Tc = Tn;
            }
            float feat = acc * inv_b;
            float e = __expf(2.0f * feat);
            float z = __fdividef(e - 1.0f, e + 1.0f);
            float o = fmaf(s_k[F_DIM + fb], z, s_k[fb]);
            float z2 = 2.0f * z;
            float Up = 1.0f, Uc = z;
            #pragma unroll
            for (int k = 2; k < KDEG; k++) {
                float Un = fmaf(z2, Uc, -Up);
                o = fmaf(s_k[k * F_DIM + fb], Un, o);
                Up = Uc; Uc = Un;
            }
            part += o;
        }
        // Warp reduction over 64 features (32 lanes x 2).
        #pragma unroll
        for (int off = 16; off; off >>= 1)
            part += __shfl_xor_sync(0xffffffffu, part, off);
        if (lane == 0) out[row0 + r] = part;
    }
}

extern "C" void kernel_launch(void* const* d_in, const int* in_sizes, int n_in,
                              void* d_out, int out_size) {
    const float* X = (const float*)d_in[0];
    const float* W = (const float*)d_in[1];
    const float* C = (const float*)d_in[2];
    float* out = (float*)d_out;

    const int rows_per_block = WARPS_PER_BLOCK * ROWS_PER_WARP;   // 32
    const int grid = B_TOTAL / rows_per_block;                    // 2048
    qkan_kernel<<<grid, THREADS>>>(X, W, C, out);
}

// round 2
// speedup vs baseline: 1.4980x; 1.4980x over previous
#include <cuda_runtime.h>
#include <cuda_bf16.h>

// QuantumKANRegressor on sm_100a.
// out[b] = sum_f  KAN( tanh( (sum_d W[f][d] T_d(X[b][f])) / sum_d |W[f][d]| ), C[f][:] )
// Packed f32x2 path: each lane owns features (2*lane, 2*lane+1).
// Sign-absorbed Chebyshev recurrence: B_{d+1} = m_d * B_d + B_{d-1}, m alternating
// (-2x, +2x), gives B_d = s_d T_d with s_d = (d&2)?-1:+1; s_d and 1/den folded
// into register weights, so the main loop is pure packed FMAs.

#define F_DIM   64
#define DEG     16
#define KC      6        // KAN_DEG + 1
#define THREADS 256
#define WARPS   8
#define ROWS    8        // rows per warp
#define B_TOTAL 65536

typedef unsigned long long u64;

static __device__ __forceinline__ u64 pk(float lo, float hi) {
    u64 r; asm("mov.b64 %0, {%1, %2};" : "=l"(r) : "f"(lo), "f"(hi)); return r;
}
static __device__ __forceinline__ void upk(u64 v, float& lo, float& hi) {
    asm("mov.b64 {%0, %1}, %2;" : "=f"(lo), "=f"(hi) : "l"(v));
}
static __device__ __forceinline__ u64 fma2(u64 a, u64 b, u64 c) {
    u64 d; asm("fma.rn.f32x2 %0, %1, %2, %3;" : "=l"(d) : "l"(a), "l"(b), "l"(c)); return d;
}
static __device__ __forceinline__ u64 mul2(u64 a, u64 b) {
    u64 d; asm("mul.rn.f32x2 %0, %1, %2;" : "=l"(d) : "l"(a), "l"(b)); return d;
}
static __device__ __forceinline__ u64 add2(u64 a, u64 b) {
    u64 d; asm("add.rn.f32x2 %0, %1, %2;" : "=l"(d) : "l"(a), "l"(b)); return d;
}

static __device__ __forceinline__ float tanh_fast(float f) {
    // tanh(f) = 1 - 2/(exp(2f)+1); |f| <= 1 here.
    float e = __expf(2.0f * f);
    return 1.0f - __fdividef(2.0f, e + 1.0f);
}

__global__ void __launch_bounds__(THREADS)
qkan2_kernel(const float* __restrict__ X,
             const float* __restrict__ W,     // [64][16]
             const float* __restrict__ C,     // [64][6]
             float* __restrict__ out)
{
    __shared__ float s_w[DEG][F_DIM];   // sign * inv_den folded in
    __shared__ float s_c[KC][F_DIM];    // sign folded in

    const int tid = threadIdx.x;

    if (tid < F_DIM) {
        float wloc[DEG];
        float den = 0.0f;
        #pragma unroll
        for (int d = 0; d < DEG; d++) { wloc[d] = W[tid * DEG + d]; den += fabsf(wloc[d]); }
        const float inv = 1.0f / den;
        #pragma unroll
        for (int d = 0; d < DEG; d++) {
            // weight index d corresponds to T_{d+1}; s_{d+1} = ((d+1)&2)? -1 : +1
            float s = ((d + 1) & 2) ? -inv : inv;
            s_w[d][tid] = wloc[d] * s;
        }
        #pragma unroll
        for (int k = 0; k < KC; k++) {
            float s = (k & 2) ? -1.0f : 1.0f;
            s_c[k][tid] = C[tid * KC + k] * s;
        }
    }
    __syncthreads();

    const int lane = tid & 31;
    const int warp = tid >> 5;

    // Per-thread register weights for the packed feature pair (2*lane, 2*lane+1).
    u64 rw[DEG], rc[KC];
    #pragma unroll
    for (int d = 0; d < DEG; d++) rw[d] = ((const u64*)s_w[d])[lane];
    #pragma unroll
    for (int k = 0; k < KC; k++)  rc[k] = ((const u64*)s_c[k])[lane];

    const int row0 = (blockIdx.x * WARPS + warp) * ROWS;
    const u64* Xp = (const u64*)X;

    // Batch all row loads (MLP = ROWS).
    u64 xv[ROWS];
    #pragma unroll
    for (int r = 0; r < ROWS; r++)
        xv[r] = Xp[(size_t)(row0 + r) * (F_DIM / 2) + lane];

    const u64 ONE2  = 0x3f8000003f800000ULL;   // (1.0f, 1.0f)
    const u64 NEG2  = 0xc0000000c0000000ULL;   // (-2.0f, -2.0f)

    #pragma unroll
    for (int r = 0; r < ROWS; r++) {
        const u64 x   = xv[r];
        const u64 x2  = add2(x, x);
        const u64 nx2 = mul2(x, NEG2);

        // QSVT: acc = sum_{d=1..16} w'_d B_d, B_d = s_d T_d(x)
        u64 Bp = ONE2;               // B_0
        u64 Bc = x;                  // B_1
        u64 acc = mul2(rw[0], Bc);
        #pragma unroll
        for (int i = 1; i < DEG; i++) {
            u64 Bn = fma2((i & 1) ? nx2 : x2, Bc, Bp);   // B_{i+1}
            acc = fma2(rw[i], Bn, acc);
            Bp = Bc; Bc = Bn;
        }
        // acc == feat (inv_den folded into rw)

        float f0, f1; upk(acc, f0, f1);
        const float t0 = tanh_fast(f0);
        const float t1 = tanh_fast(f1);
        const u64 z   = pk(t0, t1);
        const u64 z2  = add2(z, z);
        const u64 nz2 = mul2(z, NEG2);

        // KAN: o = sum_{k=0..5} c'_k B_k(z)
        u64 Kp = ONE2;               // B_0
        u64 Kc = z;                  // B_1
        u64 o  = fma2(rc[1], z, rc[0]);
        #pragma unroll
        for (int k = 1; k < KC - 1; k++) {
            u64 Kn = fma2((k & 1) ? nz2 : z2, Kc, Kp);   // B_{k+1}
            o = fma2(rc[k + 1], Kn, o);
            Kp = Kc; Kc = Kn;
        }

        float o0, o1; upk(o, o0, o1);
        float part = o0 + o1;
        #pragma unroll
        for (int off = 16; off; off >>= 1)
            part += __shfl_xor_sync(0xffffffffu, part, off);
        if (lane == 0) out[row0 + r] = part;
    }
}

extern "C" void kernel_launch(void* const* d_in, const int* in_sizes, int n_in,
                              void* d_out, int out_size) {
    const float* X = (const float*)d_in[0];
    const float* W = (const float*)d_in[1];
    const float* C = (const float*)d_in[2];
    float* out = (float*)d_out;

    const int rows_per_block = WARPS * ROWS;              // 64
    const int grid = B_TOTAL / rows_per_block;            // 1024
    qkan2_kernel<<<grid, THREADS>>>(X, W, C, out);
}